// round 1
// baseline (speedup 1.0000x reference)
#include <cuda_runtime.h>
#include <cstdint>
#include <cstddef>

#define N 8192
#define D 256
#define BM 64
#define BN 64

// Scratch (no runtime allocation allowed)
__device__ float g_Wh[(size_t)N * D];
__device__ float g_fs[N];
__device__ float g_fd[N];

typedef unsigned long long u64;

__device__ __forceinline__ u64 pack2(float a, float b) {
    u64 r; asm("mov.b64 %0, {%1, %2};" : "=l"(r) : "f"(a), "f"(b)); return r;
}
__device__ __forceinline__ void unpack2(u64 v, float &a, float &b) {
    asm("mov.b64 {%0, %1}, %2;" : "=f"(a), "=f"(b) : "l"(v));
}
__device__ __forceinline__ u64 fma2(u64 a, u64 b, u64 c) {
    u64 r; asm("fma.rn.f32x2 %0, %1, %2, %3;" : "=l"(r) : "l"(a), "l"(b), "l"(c)); return r;
}
__device__ __forceinline__ u64 mul2(u64 a, u64 b) {
    u64 r; asm("mul.rn.f32x2 %0, %1, %2;" : "=l"(r) : "l"(a), "l"(b)); return r;
}

// ---------------------------------------------------------------------------
// Kernel 1: Wh = X @ W   (64 rows per CTA, 256 threads, f32x2 FFMA)
// thread (r = tid>>2, g = tid&3) owns row r, dims [g*64, g*64+64)
// ---------------------------------------------------------------------------
__global__ __launch_bounds__(256, 1) void gemm_wh_kernel(
    const float* __restrict__ X, const float* __restrict__ W) {
    __shared__ float Xs[64][33];
    __shared__ float Ws[32 * 256];
    const int tid = threadIdx.x;
    const int r = tid >> 2, g = tid & 3;
    const int row0 = blockIdx.x * 64;

    u64 acc[32];
#pragma unroll
    for (int i = 0; i < 32; i++) acc[i] = 0ull;

    for (int k0 = 0; k0 < D; k0 += 32) {
        __syncthreads();
        // X tile: 64 rows x 32 k  (512 float4, 2 per thread)
#pragma unroll
        for (int i = 0; i < 2; i++) {
            int f = i * 256 + tid;
            int xr = f >> 3, k4 = (f & 7) << 2;
            float4 v = *(const float4*)&X[(size_t)(row0 + xr) * D + k0 + k4];
            Xs[xr][k4 + 0] = v.x; Xs[xr][k4 + 1] = v.y;
            Xs[xr][k4 + 2] = v.z; Xs[xr][k4 + 3] = v.w;
        }
        // W tile: 32 k x 256 d  (2048 float4, 8 per thread)
#pragma unroll
        for (int i = 0; i < 8; i++) {
            int f = i * 256 + tid;
            int kk = f >> 6, d4 = (f & 63) << 2;
            *(float4*)&Ws[kk * 256 + d4] = *(const float4*)&W[(size_t)(k0 + kk) * D + d4];
        }
        __syncthreads();

#pragma unroll 4
        for (int k = 0; k < 32; k++) {
            float x = Xs[r][k];
            u64 x2 = pack2(x, x);
            const ulonglong2* wrow = (const ulonglong2*)&Ws[k * 256 + g * 64];
#pragma unroll
            for (int d = 0; d < 16; d++) {
                ulonglong2 w = wrow[d];
                acc[2 * d + 0] = fma2(w.x, x2, acc[2 * d + 0]);
                acc[2 * d + 1] = fma2(w.y, x2, acc[2 * d + 1]);
            }
        }
    }
    float* o = &g_Wh[(size_t)(row0 + r) * D + g * 64];
#pragma unroll
    for (int d2 = 0; d2 < 32; d2 += 2) {
        float4 v;
        unpack2(acc[d2], v.x, v.y);
        unpack2(acc[d2 + 1], v.z, v.w);
        *(float4*)&o[d2 * 2] = v;
    }
}

// ---------------------------------------------------------------------------
// Kernel 2: f_src[i] = Wh_i . a_src ; f_dst[i] = Wh_i . a_dst
// one warp per row
// ---------------------------------------------------------------------------
__global__ __launch_bounds__(256, 1) void fsfd_kernel(
    const float* __restrict__ a_src, const float* __restrict__ a_dst) {
    const int warp = threadIdx.x >> 5, lane = threadIdx.x & 31;
    const int row = blockIdx.x * 8 + warp;
    const float* wh = &g_Wh[(size_t)row * D];
    float s = 0.f, t = 0.f;
#pragma unroll
    for (int k = lane; k < D; k += 32) {
        float w = wh[k];
        s += w * a_src[k];
        t += w * a_dst[k];
    }
#pragma unroll
    for (int o = 16; o > 0; o >>= 1) {
        s += __shfl_xor_sync(0xffffffffu, s, o);
        t += __shfl_xor_sync(0xffffffffu, t, o);
    }
    if (lane == 0) { g_fs[row] = s; g_fd[row] = t; }
}

// ---------------------------------------------------------------------------
// Kernel 3: fused masked-softmax attention + P@Wh + elu (flash-style)
// BM=64 rows/CTA, 256 threads. thread (r = tid>>2, g = tid&3):
//   - softmax phase: owns cols [g*16, g*16+16) of its row (tile of BN=64 cols)
//   - accumulate phase: owns dims [g*64, g*64+64) of its row
// ---------------------------------------------------------------------------
__global__ __launch_bounds__(256, 1) void attn_kernel(
    const int* __restrict__ adj, float* __restrict__ out) {
    extern __shared__ float smem[];
    float* whs = smem;                 // BN * D floats = 64 KB
    float* psm = smem + BN * D;        // 64 * 65 floats (padded)
    float* fds = psm + 64 * 65;        // BN floats

    const int tid = threadIdx.x;
    const int r = tid >> 2, g = tid & 3;
    const int row = blockIdx.x * BM + r;
    const int dbase = g * 64;

    const float fsr = g_fs[row];
    float m = -1e30f, l = 0.f;
    u64 acc[32];
#pragma unroll
    for (int i = 0; i < 32; i++) acc[i] = 0ull;

    const int4* arow = (const int4*)(adj + (size_t)row * N);
    int4 adjv[4];
#pragma unroll
    for (int q = 0; q < 4; q++) adjv[q] = arow[g * 4 + q];   // tile 0 prefetch

    for (int j0 = 0; j0 < N; j0 += BN) {
        // ---- load Wh tile (BN x D) + f_dst slice ----
#pragma unroll
        for (int i = 0; i < 16; i++) {
            int f = i * 256 + tid;
            int c = f >> 6, d4 = (f & 63) << 2;
            *(float4*)&whs[c * D + d4] =
                *(const float4*)&g_Wh[(size_t)(j0 + c) * D + d4];
        }
        if (tid < BN) fds[tid] = g_fd[j0 + tid];
        __syncthreads();

        // ---- masked logits + online softmax ----
        float ev[16];
        float mloc = -1e30f;
#pragma unroll
        for (int q = 0; q < 4; q++) {
            int aa[4] = {adjv[q].x, adjv[q].y, adjv[q].z, adjv[q].w};
#pragma unroll
            for (int t = 0; t < 4; t++) {
                int i = q * 4 + t;
                float e = -1e30f;
                if (aa[t] > 0) {
                    e = fsr + fds[g * 16 + i];
                    e = e > 0.f ? e : 0.2f * e;      // leaky_relu(0.2)
                }
                ev[i] = e;
                mloc = fmaxf(mloc, e);
            }
        }
        mloc = fmaxf(mloc, __shfl_xor_sync(0xffffffffu, mloc, 1));
        mloc = fmaxf(mloc, __shfl_xor_sync(0xffffffffu, mloc, 2));
        float mn = fmaxf(m, mloc);
        float scale = __expf(m - mn);
        float ssum = 0.f;
#pragma unroll
        for (int i = 0; i < 16; i++) {
            float p = (ev[i] > -1e29f) ? __expf(ev[i] - mn) : 0.f;
            psm[r * 65 + g * 16 + i] = p;
            ssum += p;
        }
        ssum += __shfl_xor_sync(0xffffffffu, ssum, 1);
        ssum += __shfl_xor_sync(0xffffffffu, ssum, 2);
        l = l * scale + ssum;
        m = mn;
        u64 s2 = pack2(scale, scale);
#pragma unroll
        for (int k = 0; k < 32; k++) acc[k] = mul2(acc[k], s2);

        // ---- prefetch next adjacency tile (hide DRAM latency) ----
        if (j0 + BN < N) {
#pragma unroll
            for (int q = 0; q < 4; q++)
                adjv[q] = arow[(j0 + BN) / 4 + g * 4 + q];
        }
        __syncwarp();   // psm produced/consumed by same warp's lanes

        // ---- accumulate: acc += p_c * Wh[c, dbase..dbase+64) ----
        const ulonglong2* wh2base = (const ulonglong2*)whs;
#pragma unroll 4
        for (int c = 0; c < BN; c++) {
            float p = psm[r * 65 + c];
            u64 p2 = pack2(p, p);
            const ulonglong2* wrow = wh2base + (c * D + dbase) / 4;
#pragma unroll
            for (int d = 0; d < 16; d++) {
                ulonglong2 w = wrow[d];
                acc[2 * d + 0] = fma2(w.x, p2, acc[2 * d + 0]);
                acc[2 * d + 1] = fma2(w.y, p2, acc[2 * d + 1]);
            }
        }
        __syncthreads();  // whs fully consumed before next tile load
    }

    // ---- epilogue: normalize + elu ----
    float inv = 1.f / l;
    float* o = &out[(size_t)row * D + dbase];
#pragma unroll
    for (int d2 = 0; d2 < 32; d2 += 2) {
        float v[4];
        unpack2(acc[d2], v[0], v[1]);
        unpack2(acc[d2 + 1], v[2], v[3]);
        float4 w;
#pragma unroll
        for (int q = 0; q < 4; q++) {
            float x = v[q] * inv;
            ((float*)&w)[q] = x > 0.f ? x : expm1f(x);
        }
        *(float4*)&o[d2 * 2] = w;
    }
}

// ---------------------------------------------------------------------------
#define ATTN_SMEM ((BN * D + 64 * 65 + BN) * (int)sizeof(float))

extern "C" void kernel_launch(void* const* d_in, const int* in_sizes, int n_in,
                              void* d_out, int out_size) {
    const float* X     = (const float*)d_in[0];
    const int*   adj   = (const int*)d_in[1];
    const float* W     = (const float*)d_in[2];
    const float* a_src = (const float*)d_in[3];
    const float* a_dst = (const float*)d_in[4];
    float* out = (float*)d_out;
    (void)in_sizes; (void)n_in; (void)out_size;

    cudaFuncSetAttribute(attn_kernel,
                         cudaFuncAttributeMaxDynamicSharedMemorySize, ATTN_SMEM);

    gemm_wh_kernel<<<N / 64, 256>>>(X, W);
    fsfd_kernel<<<N / 8, 256>>>(a_src, a_dst);
    attn_kernel<<<N / BM, 256, ATTN_SMEM>>>(adj, out);
}

// round 4
// speedup vs baseline: 30.3703x; 30.3703x over previous
#include <cuda_runtime.h>
#include <cuda_fp16.h>
#include <cstdint>
#include <cstddef>

#define NN 8192
#define DD 256
#define NB 264            // 256 dims + 8 halves pad -> 528B row, TMA-friendly

// ---------------- device scratch (no runtime alloc allowed) ----------------
__device__ __align__(128) __half g_Wh16[(size_t)NN * NB];
__device__ float g_fs[NN], g_fd[NN];
__device__ float g_ws[DD], g_wd[DD];
__device__ unsigned g_R2[NN];        // half2(R_i, R_i),  R = exp(-0.8 fs)
__device__ unsigned g_B2[NN / 2];    // half2(B_2j, B_2j+1), B = exp(fd)
__device__ unsigned g_D2[NN / 2];    // half2(D_2j, D_2j+1), D = exp(0.2 fd)

// ---------------- helpers ----------------
__device__ __forceinline__ uint32_t smem_u32(const void* p) {
    uint32_t a;
    asm("{ .reg .u64 t; cvta.to.shared.u64 t, %1; cvt.u32.u64 %0, t; }" : "=r"(a) : "l"(p));
    return a;
}
__device__ __forceinline__ __half2 u2h2(unsigned u) { return *reinterpret_cast<__half2*>(&u); }
__device__ __forceinline__ unsigned h22u(__half2 h) { return *reinterpret_cast<unsigned*>(&h); }

#define MBAR_INIT(mb, c) asm volatile("mbarrier.init.shared.b64 [%0], %1;" :: "r"(mb), "r"(c) : "memory")
#define EXPECT_TX(mb, n) asm volatile("mbarrier.arrive.expect_tx.shared.b64 _, [%0], %1;" :: "r"(mb), "r"(n) : "memory")
#define TMA_BULK(dst, src, bytes, mb) \
    asm volatile("cp.async.bulk.shared::cluster.global.mbarrier::complete_tx::bytes [%0], [%1], %2, [%3];" \
                 :: "r"(dst), "l"(src), "r"(bytes), "r"(mb) : "memory")

__device__ __forceinline__ void mbar_wait(uint32_t mb, uint32_t parity) {
    uint32_t done;
    asm volatile(
        "{\n\t.reg .pred p;\n\t"
        "mbarrier.try_wait.parity.shared.b64 p, [%1], %2;\n\t"
        "selp.b32 %0, 1, 0, p;\n\t}"
        : "=r"(done) : "r"(mb), "r"(parity) : "memory");
    if (!done) {
        asm volatile(
            "{\n\t.reg .pred P1;\n\t"
            "WL_%=:\n\t"
            "mbarrier.try_wait.parity.shared.b64 P1, [%0], %1;\n\t"
            "@P1 bra.uni WD_%=;\n\t"
            "bra.uni WL_%=;\n\t"
            "WD_%=:\n\t}"
            :: "r"(mb), "r"(parity) : "memory");
    }
}

__device__ __forceinline__ void ldsm4(unsigned &r0, unsigned &r1, unsigned &r2, unsigned &r3,
                                      uint32_t addr) {
    asm volatile("ldmatrix.sync.aligned.m8n8.x4.shared.b16 {%0,%1,%2,%3}, [%4];"
                 : "=r"(r0), "=r"(r1), "=r"(r2), "=r"(r3) : "r"(addr));
}
__device__ __forceinline__ void ldsm4t(unsigned &r0, unsigned &r1, unsigned &r2, unsigned &r3,
                                       uint32_t addr) {
    asm volatile("ldmatrix.sync.aligned.m8n8.x4.trans.shared.b16 {%0,%1,%2,%3}, [%4];"
                 : "=r"(r0), "=r"(r1), "=r"(r2), "=r"(r3) : "r"(addr));
}
__device__ __forceinline__ void mma16816(float* c, unsigned a0, unsigned a1, unsigned a2,
                                         unsigned a3, unsigned b0, unsigned b1) {
    asm volatile(
        "mma.sync.aligned.m16n8k16.row.col.f32.f16.f16.f32 "
        "{%0,%1,%2,%3}, {%4,%5,%6,%7}, {%8,%9}, {%0,%1,%2,%3};"
        : "+f"(c[0]), "+f"(c[1]), "+f"(c[2]), "+f"(c[3])
        : "r"(a0), "r"(a1), "r"(a2), "r"(a3), "r"(b0), "r"(b1));
}

// ---------------------------------------------------------------------------
// wvec: w_src = W @ a_src ; w_dst = W @ a_dst   (1 CTA, 256 thr)
// ---------------------------------------------------------------------------
__global__ void wvec_kernel(const float* __restrict__ W, const float* __restrict__ a_src,
                            const float* __restrict__ a_dst) {
    int i = threadIdx.x;
    float s = 0.f, t = 0.f;
    const float4* wr = (const float4*)&W[(size_t)i * DD];
#pragma unroll 8
    for (int o = 0; o < DD / 4; o++) {
        float4 w = wr[o];
        float4 as = *(const float4*)&a_src[o * 4];
        float4 ad = *(const float4*)&a_dst[o * 4];
        s += w.x * as.x + w.y * as.y + w.z * as.z + w.w * as.w;
        t += w.x * ad.x + w.y * ad.y + w.z * ad.z + w.w * ad.w;
    }
    g_ws[i] = s;
    g_wd[i] = t;
}

// ---------------------------------------------------------------------------
// fsfd: fs = X @ w_src ; fd = X @ w_dst   (one warp per row, fp32)
// ---------------------------------------------------------------------------
__global__ __launch_bounds__(256) void fsfd_kernel(const float* __restrict__ X) {
    const int warp = threadIdx.x >> 5, lane = threadIdx.x & 31;
    const int row = blockIdx.x * 8 + warp;
    const float* xr = &X[(size_t)row * DD];
    float s = 0.f, t = 0.f;
#pragma unroll
    for (int k = lane; k < DD; k += 32) {
        float x = xr[k];
        s += x * g_ws[k];
        t += x * g_wd[k];
    }
#pragma unroll
    for (int o = 16; o > 0; o >>= 1) {
        s += __shfl_xor_sync(0xffffffffu, s, o);
        t += __shfl_xor_sync(0xffffffffu, t, o);
    }
    if (lane == 0) { g_fs[row] = s; g_fd[row] = t; }
}

// ---------------------------------------------------------------------------
// consts: R2[i] = half2(exp(-0.8 fs_i)); B2/D2 packed per col pair
// ---------------------------------------------------------------------------
__global__ void consts_kernel() {
    int i = blockIdx.x * 256 + threadIdx.x;
    float fs = g_fs[i];
    __half r = __float2half_rn(__expf(-0.8f * fs));
    g_R2[i] = h22u(__halves2half2(r, r));
    if (i < NN / 2) {
        float f0 = g_fd[2 * i], f1 = g_fd[2 * i + 1];
        g_B2[i] = h22u(__floats2half2_rn(__expf(f0), __expf(f1)));
        g_D2[i] = h22u(__floats2half2_rn(__expf(0.2f * f0), __expf(0.2f * f1)));
    }
}

// ---------------------------------------------------------------------------
// K1: Wh16 = fp16(X) @ fp16(W)  via mma.sync, fp32 accum -> fp16 out [NN][NB]
// grid 128 x 256 thr; BM=64; warps 2m x 4n (warp tile 32 x 64)
// ---------------------------------------------------------------------------
__global__ __launch_bounds__(256) void wh_gemm_kernel(const float* __restrict__ X,
                                                      const float* __restrict__ W) {
    __shared__ __align__(16) __half Xs[64 * 72];
    __shared__ __align__(16) __half Wsm[64 * 264];
    const int tid = threadIdx.x;
    const int warp = tid >> 5, lane = tid & 31;
    const int wm = warp >> 2, wn = warp & 3;
    const int row0 = blockIdx.x * 64;

    float c[2][8][4];
#pragma unroll
    for (int a = 0; a < 2; a++)
#pragma unroll
        for (int b = 0; b < 8; b++)
#pragma unroll
            for (int d = 0; d < 4; d++) c[a][b][d] = 0.f;

    for (int kt = 0; kt < 4; kt++) {
        // X tile [64 rows][64 k] fp32 -> fp16
#pragma unroll
        for (int i = 0; i < 4; i++) {
            int f = i * 1024 + tid * 4;
            int r = f >> 6, cl = f & 63;
            float4 v = *(const float4*)&X[(size_t)(row0 + r) * DD + kt * 64 + cl];
            unsigned h0 = h22u(__floats2half2_rn(v.x, v.y));
            unsigned h1 = h22u(__floats2half2_rn(v.z, v.w));
            *(uint2*)&Xs[r * 72 + cl] = make_uint2(h0, h1);
        }
        // W tile [64 k][256 n] fp32 -> fp16
#pragma unroll
        for (int i = 0; i < 16; i++) {
            int f = i * 1024 + tid * 4;
            int r = f >> 8, cl = f & 255;
            float4 v = *(const float4*)&W[(size_t)(kt * 64 + r) * DD + cl];
            unsigned h0 = h22u(__floats2half2_rn(v.x, v.y));
            unsigned h1 = h22u(__floats2half2_rn(v.z, v.w));
            *(uint2*)&Wsm[r * 264 + cl] = make_uint2(h0, h1);
        }
        __syncthreads();

#pragma unroll
        for (int ks = 0; ks < 4; ks++) {
            unsigned a[2][4];
#pragma unroll
            for (int mt = 0; mt < 2; mt++)
                ldsm4(a[mt][0], a[mt][1], a[mt][2], a[mt][3],
                      smem_u32(&Xs[(wm * 32 + mt * 16 + (lane & 15)) * 72 +
                                   ks * 16 + ((lane >> 4) << 3)]));
#pragma unroll
            for (int np = 0; np < 4; np++) {
                unsigned b0, b1, b2, b3;
                ldsm4t(b0, b1, b2, b3,
                       smem_u32(&Wsm[(ks * 16 + (lane & 15)) * 264 +
                                     wn * 64 + np * 16 + ((lane >> 4) << 3)]));
#pragma unroll
                for (int mt = 0; mt < 2; mt++) {
                    mma16816(c[mt][np * 2], a[mt][0], a[mt][1], a[mt][2], a[mt][3], b0, b1);
                    mma16816(c[mt][np * 2 + 1], a[mt][0], a[mt][1], a[mt][2], a[mt][3], b2, b3);
                }
            }
        }
        __syncthreads();
    }

    const int g = lane >> 2, tq = lane & 3;
#pragma unroll
    for (int mt = 0; mt < 2; mt++)
#pragma unroll
        for (int nb = 0; nb < 8; nb++) {
            int row = row0 + wm * 32 + mt * 16 + g;
            int col = wn * 64 + nb * 8 + tq * 2;
            *(unsigned*)&g_Wh16[(size_t)row * NB + col] =
                h22u(__floats2half2_rn(c[mt][nb][0], c[mt][nb][1]));
            *(unsigned*)&g_Wh16[(size_t)(row + 8) * NB + col] =
                h22u(__floats2half2_rn(c[mt][nb][2], c[mt][nb][3]));
        }
    if (tid < 64) {
        uint4 z = make_uint4(0, 0, 0, 0);
        *(uint4*)&g_Wh16[(size_t)(row0 + tid) * NB + 256] = z;   // pad cols
    }
}

// ---------------------------------------------------------------------------
// K3: fused edge-gen + masked softmax + P@Wh + elu
// grid 128 x 256 thr; BM=64 rows/CTA; 128 col tiles of 64
// smem: mbar0@0 mbar1@8, l4@16 (1KB), Ps@1056 (64x72 half), Bs0@10496, Bs1@44288
// ---------------------------------------------------------------------------
#define MB0 0
#define MB1 8
#define L4O 16
#define PSO 1056
#define BS0O 10496
#define BS1O (10496 + 33792)
#define K3_SMEM (BS1O + 33792)
#define BTILE 33792u   // 64 rows * 264 halves * 2B

__global__ __launch_bounds__(256, 1) void attn_kernel(const int* __restrict__ adj,
                                                      float* __restrict__ out) {
    extern __shared__ __align__(128) char sm[];
    const uint32_t base = smem_u32(sm);
    __half* Ps = (__half*)(sm + PSO);
    float* l4 = (float*)(sm + L4O);

    const int tid = threadIdx.x;
    const int warp = tid >> 5, lane = tid & 31;
    const int wm = warp >> 2, wn = warp & 3;
    const int r = tid >> 2, q = tid & 3;
    const int row0 = blockIdx.x * 64;

    if (tid == 0) { MBAR_INIT(base + MB0, 1); MBAR_INIT(base + MB1, 1); }
    __syncthreads();

    const __half2 R2h = u2h2(g_R2[row0 + r]);
    const int4* arow = (const int4*)(adj + (size_t)(row0 + r) * NN);
    int4 av[4];
#pragma unroll
    for (int u = 0; u < 4; u++) av[u] = __ldcs(&arow[q * 4 + u]);   // tile 0

    if (tid == 0) {
        EXPECT_TX(base + MB0, BTILE);
        TMA_BULK(base + BS0O, (const void*)&g_Wh16[0], BTILE, base + MB0);
    }

    float lacc = 0.f;
    int ph0 = 0, ph1 = 0;
    float c[2][8][4];
#pragma unroll
    for (int a = 0; a < 2; a++)
#pragma unroll
        for (int b = 0; b < 8; b++)
#pragma unroll
            for (int d = 0; d < 4; d++) c[a][b][d] = 0.f;

    for (int t = 0; t < NN / 64; t++) {
        const int b = t & 1;

        // ---- kick TMA for t+1 into the other buffer ----
        if (t + 1 < NN / 64 && tid == 0) {
            uint32_t mb = base + ((1 - b) ? MB1 : MB0);
            uint32_t bs = base + ((1 - b) ? BS1O : BS0O);
            EXPECT_TX(mb, BTILE);
            TMA_BULK(bs, (const void*)&g_Wh16[(size_t)(t + 1) * 64 * NB], BTILE, mb);
        }

        // ---- edge-gen: p = mask * max(B, R*D), fp16; lacc in fp32 ----
        uint4 bA = *(const uint4*)&g_B2[t * 32 + q * 8];
        uint4 bB = *(const uint4*)&g_B2[t * 32 + q * 8 + 4];
        uint4 dA = *(const uint4*)&g_D2[t * 32 + q * 8];
        uint4 dB = *(const uint4*)&g_D2[t * 32 + q * 8 + 4];
        unsigned bb[8] = {bA.x, bA.y, bA.z, bA.w, bB.x, bB.y, bB.z, bB.w};
        unsigned dd[8] = {dA.x, dA.y, dA.z, dA.w, dB.x, dB.y, dB.z, dB.w};
#pragma unroll
        for (int u = 0; u < 4; u++) {
            int4 a4 = av[u];
            unsigned mka = (a4.x > 0 ? 0x3C00u : 0u) | (a4.y > 0 ? 0x3C000000u : 0u);
            unsigned mkb = (a4.z > 0 ? 0x3C00u : 0u) | (a4.w > 0 ? 0x3C000000u : 0u);
            __half2 pa = __hmul2(__hmax2(u2h2(bb[u * 2]), __hmul2(R2h, u2h2(dd[u * 2]))),
                                 u2h2(mka));
            __half2 pb = __hmul2(__hmax2(u2h2(bb[u * 2 + 1]), __hmul2(R2h, u2h2(dd[u * 2 + 1]))),
                                 u2h2(mkb));
            *(uint2*)&Ps[r * 72 + q * 16 + u * 4] = make_uint2(h22u(pa), h22u(pb));
            float2 fa = __half22float2(pa), fb = __half22float2(pb);
            lacc += fa.x + fa.y + fb.x + fb.y;
        }

        // ---- prefetch adjacency for t+1 ----
        if (t + 1 < NN / 64) {
#pragma unroll
            for (int u = 0; u < 4; u++)
                av[u] = __ldcs(&arow[(t + 1) * 16 + q * 4 + u]);
        }

        // ---- wait B tile t, then sync so Ps is visible ----
        if (b == 0) { mbar_wait(base + MB0, ph0); ph0 ^= 1; }
        else        { mbar_wait(base + MB1, ph1); ph1 ^= 1; }
        __syncthreads();

        // ---- MMA: c += P[64x64] @ B[64k x 256n] ----
        const __half* Bs = (const __half*)(sm + (b ? BS1O : BS0O));
#pragma unroll
        for (int ks = 0; ks < 4; ks++) {
            unsigned a[2][4];
#pragma unroll
            for (int mt = 0; mt < 2; mt++)
                ldsm4(a[mt][0], a[mt][1], a[mt][2], a[mt][3],
                      smem_u32(&Ps[(wm * 32 + mt * 16 + (lane & 15)) * 72 +
                                   ks * 16 + ((lane >> 4) << 3)]));
#pragma unroll
            for (int np = 0; np < 4; np++) {
                unsigned b0, b1, b2, b3;
                ldsm4t(b0, b1, b2, b3,
                       smem_u32(&Bs[(ks * 16 + (lane & 15)) * 264 +
                                    wn * 64 + np * 16 + ((lane >> 4) << 3)]));
#pragma unroll
                for (int mt = 0; mt < 2; mt++) {
                    mma16816(c[mt][np * 2], a[mt][0], a[mt][1], a[mt][2], a[mt][3], b0, b1);
                    mma16816(c[mt][np * 2 + 1], a[mt][0], a[mt][1], a[mt][2], a[mt][3], b2, b3);
                }
            }
        }
        __syncthreads();   // Ps + Bs consumed before next iter overwrites
    }

    // ---- row-sum reduction ----
    l4[r * 4 + q] = lacc;
    __syncthreads();

    // ---- epilogue: normalize + elu + store ----
#pragma unroll
    for (int mt = 0; mt < 2; mt++) {
        int rl = wm * 32 + mt * 16 + (lane >> 2);
        float4 lv1 = *(float4*)&l4[rl * 4];
        float4 lv2 = *(float4*)&l4[(rl + 8) * 4];
        float inv1 = 1.f / (lv1.x + lv1.y + lv1.z + lv1.w);
        float inv2 = 1.f / (lv2.x + lv2.y + lv2.z + lv2.w);
#pragma unroll
        for (int nb = 0; nb < 8; nb++) {
            int col = wn * 64 + nb * 8 + (lane & 3) * 2;
            float x0 = c[mt][nb][0] * inv1, x1 = c[mt][nb][1] * inv1;
            float y0 = c[mt][nb][2] * inv2, y1 = c[mt][nb][3] * inv2;
            float2 v1 = make_float2(x0 > 0.f ? x0 : expm1f(x0),
                                    x1 > 0.f ? x1 : expm1f(x1));
            float2 v2 = make_float2(y0 > 0.f ? y0 : expm1f(y0),
                                    y1 > 0.f ? y1 : expm1f(y1));
            *(float2*)&out[(size_t)(row0 + rl) * DD + col] = v1;
            *(float2*)&out[(size_t)(row0 + rl + 8) * DD + col] = v2;
        }
    }
}

// ---------------------------------------------------------------------------
extern "C" void kernel_launch(void* const* d_in, const int* in_sizes, int n_in,
                              void* d_out, int out_size) {
    const float* X     = (const float*)d_in[0];
    const int*   adj   = (const int*)d_in[1];
    const float* W     = (const float*)d_in[2];
    const float* a_src = (const float*)d_in[3];
    const float* a_dst = (const float*)d_in[4];
    float* out = (float*)d_out;
    (void)in_sizes; (void)n_in; (void)out_size;

    cudaFuncSetAttribute(attn_kernel,
                         cudaFuncAttributeMaxDynamicSharedMemorySize, K3_SMEM);

    wvec_kernel<<<1, 256>>>(W, a_src, a_dst);
    fsfd_kernel<<<NN / 8, 256>>>(X);
    consts_kernel<<<NN / 256, 256>>>();
    wh_gemm_kernel<<<NN / 64, 256>>>(X, W);
    attn_kernel<<<NN / 64, 256, K3_SMEM>>>(adj, out);
}

// round 5
// speedup vs baseline: 32.8715x; 1.0824x over previous
#include <cuda_runtime.h>
#include <cuda_fp16.h>
#include <cstdint>
#include <cstddef>

#define NN 8192
#define DD 256
#define NB 264            // 256 dims + 8 halves pad -> 528B row

// ---------------- device scratch (no runtime alloc allowed) ----------------
__device__ __align__(128) __half g_Wh16[(size_t)NN * NB];
__device__ __align__(128) __half g_X16[(size_t)NN * DD];
__device__ __align__(128) __half g_W16[DD * DD];
__device__ float g_fs[NN], g_fd[NN];
__device__ float g_ws[DD], g_wd[DD];
__device__ unsigned g_R2[NN];        // half2(R_i, R_i),  R = exp(-0.8 fs)
__device__ unsigned g_B2[NN / 2];    // half2(B_2j, B_2j+1), B = exp(fd)
__device__ unsigned g_D2[NN / 2];    // half2(D_2j, D_2j+1), D = exp(0.2 fd)

// ---------------- helpers ----------------
__device__ __forceinline__ uint32_t smem_u32(const void* p) {
    uint32_t a;
    asm("{ .reg .u64 t; cvta.to.shared.u64 t, %1; cvt.u32.u64 %0, t; }" : "=r"(a) : "l"(p));
    return a;
}
__device__ __forceinline__ __half2 u2h2(unsigned u) { return *reinterpret_cast<__half2*>(&u); }
__device__ __forceinline__ unsigned h22u(__half2 h) { return *reinterpret_cast<unsigned*>(&h); }

#define CP16(dst, src)   asm volatile("cp.async.cg.shared.global [%0], [%1], 16;" :: "r"(dst), "l"(src))
#define CPCOMMIT()       asm volatile("cp.async.commit_group;" ::: "memory")
#define CPWAIT0()        asm volatile("cp.async.wait_group 0;" ::: "memory")
#define MBAR_INIT(mb, c) asm volatile("mbarrier.init.shared.b64 [%0], %1;" :: "r"(mb), "r"(c) : "memory")
#define EXPECT_TX(mb, n) asm volatile("mbarrier.arrive.expect_tx.shared.b64 _, [%0], %1;" :: "r"(mb), "r"(n) : "memory")
#define TMA_BULK(dst, src, bytes, mb) \
    asm volatile("cp.async.bulk.shared::cluster.global.mbarrier::complete_tx::bytes [%0], [%1], %2, [%3];" \
                 :: "r"(dst), "l"(src), "r"(bytes), "r"(mb) : "memory")

__device__ __forceinline__ void mbar_wait(uint32_t mb, uint32_t parity) {
    uint32_t done;
    asm volatile(
        "{\n\t.reg .pred p;\n\t"
        "mbarrier.try_wait.parity.shared.b64 p, [%1], %2;\n\t"
        "selp.b32 %0, 1, 0, p;\n\t}"
        : "=r"(done) : "r"(mb), "r"(parity) : "memory");
    if (!done) {
        asm volatile(
            "{\n\t.reg .pred P1;\n\t"
            "WL_%=:\n\t"
            "mbarrier.try_wait.parity.shared.b64 P1, [%0], %1;\n\t"
            "@P1 bra.uni WD_%=;\n\t"
            "bra.uni WL_%=;\n\t"
            "WD_%=:\n\t}"
            :: "r"(mb), "r"(parity) : "memory");
    }
}

__device__ __forceinline__ void ldsm4(unsigned &r0, unsigned &r1, unsigned &r2, unsigned &r3,
                                      uint32_t addr) {
    asm volatile("ldmatrix.sync.aligned.m8n8.x4.shared.b16 {%0,%1,%2,%3}, [%4];"
                 : "=r"(r0), "=r"(r1), "=r"(r2), "=r"(r3) : "r"(addr));
}
__device__ __forceinline__ void ldsm4t(unsigned &r0, unsigned &r1, unsigned &r2, unsigned &r3,
                                       uint32_t addr) {
    asm volatile("ldmatrix.sync.aligned.m8n8.x4.trans.shared.b16 {%0,%1,%2,%3}, [%4];"
                 : "=r"(r0), "=r"(r1), "=r"(r2), "=r"(r3) : "r"(addr));
}
__device__ __forceinline__ void mma16816(float* c, unsigned a0, unsigned a1, unsigned a2,
                                         unsigned a3, unsigned b0, unsigned b1) {
    asm volatile(
        "mma.sync.aligned.m16n8k16.row.col.f32.f16.f16.f32 "
        "{%0,%1,%2,%3}, {%4,%5,%6,%7}, {%8,%9}, {%0,%1,%2,%3};"
        : "+f"(c[0]), "+f"(c[1]), "+f"(c[2]), "+f"(c[3])
        : "r"(a0), "r"(a1), "r"(a2), "r"(a3), "r"(b0), "r"(b1));
}

// ---------------------------------------------------------------------------
// converts: fp32 -> fp16 (vectorized)
// ---------------------------------------------------------------------------
__global__ void conv_x_kernel(const float* __restrict__ X) {
    size_t i = ((size_t)blockIdx.x * 256 + threadIdx.x) * 8;
    float4 v0 = *(const float4*)&X[i];
    float4 v1 = *(const float4*)&X[i + 4];
    uint4 o;
    o.x = h22u(__floats2half2_rn(v0.x, v0.y));
    o.y = h22u(__floats2half2_rn(v0.z, v0.w));
    o.z = h22u(__floats2half2_rn(v1.x, v1.y));
    o.w = h22u(__floats2half2_rn(v1.z, v1.w));
    *(uint4*)&g_X16[i] = o;
}
__global__ void conv_w_kernel(const float* __restrict__ W) {
    size_t i = ((size_t)blockIdx.x * 256 + threadIdx.x) * 8;
    float4 v0 = *(const float4*)&W[i];
    float4 v1 = *(const float4*)&W[i + 4];
    uint4 o;
    o.x = h22u(__floats2half2_rn(v0.x, v0.y));
    o.y = h22u(__floats2half2_rn(v0.z, v0.w));
    o.z = h22u(__floats2half2_rn(v1.x, v1.y));
    o.w = h22u(__floats2half2_rn(v1.z, v1.w));
    *(uint4*)&g_W16[i] = o;
}

// ---------------------------------------------------------------------------
// wvec: w_src = W @ a_src ; w_dst = W @ a_dst   (1 CTA, 256 thr)
// ---------------------------------------------------------------------------
__global__ void wvec_kernel(const float* __restrict__ W, const float* __restrict__ a_src,
                            const float* __restrict__ a_dst) {
    int i = threadIdx.x;
    float s = 0.f, t = 0.f;
    const float4* wr = (const float4*)&W[(size_t)i * DD];
#pragma unroll 8
    for (int o = 0; o < DD / 4; o++) {
        float4 w = wr[o];
        float4 as = *(const float4*)&a_src[o * 4];
        float4 ad = *(const float4*)&a_dst[o * 4];
        s += w.x * as.x + w.y * as.y + w.z * as.z + w.w * as.w;
        t += w.x * ad.x + w.y * ad.y + w.z * ad.z + w.w * ad.w;
    }
    g_ws[i] = s;
    g_wd[i] = t;
}

// ---------------------------------------------------------------------------
// fsfd: fs = X @ w_src ; fd = X @ w_dst   (one warp per row, fp32)
// ---------------------------------------------------------------------------
__global__ __launch_bounds__(256) void fsfd_kernel(const float* __restrict__ X) {
    const int warp = threadIdx.x >> 5, lane = threadIdx.x & 31;
    const int row = blockIdx.x * 8 + warp;
    const float* xr = &X[(size_t)row * DD];
    float s = 0.f, t = 0.f;
#pragma unroll
    for (int k = lane; k < DD; k += 32) {
        float x = xr[k];
        s += x * g_ws[k];
        t += x * g_wd[k];
    }
#pragma unroll
    for (int o = 16; o > 0; o >>= 1) {
        s += __shfl_xor_sync(0xffffffffu, s, o);
        t += __shfl_xor_sync(0xffffffffu, t, o);
    }
    if (lane == 0) { g_fs[row] = s; g_fd[row] = t; }
}

// ---------------------------------------------------------------------------
// consts: R2[i] = half2(exp(-0.8 fs_i)); B2/D2 packed per col pair
// ---------------------------------------------------------------------------
__global__ void consts_kernel() {
    int i = blockIdx.x * 256 + threadIdx.x;
    float fs = g_fs[i];
    __half r = __float2half_rn(__expf(-0.8f * fs));
    g_R2[i] = h22u(__halves2half2(r, r));
    if (i < NN / 2) {
        float f0 = g_fd[2 * i], f1 = g_fd[2 * i + 1];
        g_B2[i] = h22u(__floats2half2_rn(__expf(f0), __expf(f1)));
        g_D2[i] = h22u(__floats2half2_rn(__expf(0.2f * f0), __expf(0.2f * f1)));
    }
}

// ---------------------------------------------------------------------------
// K1: Wh16 = X16 @ W16  via mma.sync + cp.async tiles
// grid 128 x 256 thr; BM=64; warps 2m x 4n (warp tile 32 x 64)
// ---------------------------------------------------------------------------
__global__ __launch_bounds__(256) void wh_gemm_kernel() {
    __shared__ __align__(16) __half Xs[64 * 72];
    __shared__ __align__(16) __half Wsm[64 * 264];
    const int tid = threadIdx.x;
    const int warp = tid >> 5, lane = tid & 31;
    const int wm = warp >> 2, wn = warp & 3;
    const int row0 = blockIdx.x * 64;

    float c[2][8][4];
#pragma unroll
    for (int a = 0; a < 2; a++)
#pragma unroll
        for (int b = 0; b < 8; b++)
#pragma unroll
            for (int d = 0; d < 4; d++) c[a][b][d] = 0.f;

    for (int kt = 0; kt < 4; kt++) {
#pragma unroll
        for (int i = 0; i < 2; i++) {
            int ci = i * 256 + tid;
            int r = ci >> 3, o = ci & 7;
            CP16(smem_u32(&Xs[r * 72 + o * 8]),
                 &g_X16[(size_t)(row0 + r) * DD + kt * 64 + o * 8]);
        }
#pragma unroll
        for (int i = 0; i < 8; i++) {
            int ci = i * 256 + tid;
            int r = ci >> 5, o = ci & 31;
            CP16(smem_u32(&Wsm[r * 264 + o * 8]),
                 &g_W16[(size_t)(kt * 64 + r) * DD + o * 8]);
        }
        CPCOMMIT();
        CPWAIT0();
        __syncthreads();

#pragma unroll
        for (int ks = 0; ks < 4; ks++) {
            unsigned a[2][4];
#pragma unroll
            for (int mt = 0; mt < 2; mt++)
                ldsm4(a[mt][0], a[mt][1], a[mt][2], a[mt][3],
                      smem_u32(&Xs[(wm * 32 + mt * 16 + (lane & 15)) * 72 +
                                   ks * 16 + ((lane >> 4) << 3)]));
#pragma unroll
            for (int np = 0; np < 4; np++) {
                unsigned b0, b1, b2, b3;
                ldsm4t(b0, b1, b2, b3,
                       smem_u32(&Wsm[(ks * 16 + (lane & 15)) * 264 +
                                     wn * 64 + np * 16 + ((lane >> 4) << 3)]));
#pragma unroll
                for (int mt = 0; mt < 2; mt++) {
                    mma16816(c[mt][np * 2], a[mt][0], a[mt][1], a[mt][2], a[mt][3], b0, b1);
                    mma16816(c[mt][np * 2 + 1], a[mt][0], a[mt][1], a[mt][2], a[mt][3], b2, b3);
                }
            }
        }
        __syncthreads();
    }

    const int g = lane >> 2, tq = lane & 3;
#pragma unroll
    for (int mt = 0; mt < 2; mt++)
#pragma unroll
        for (int nb = 0; nb < 8; nb++) {
            int row = row0 + wm * 32 + mt * 16 + g;
            int col = wn * 64 + nb * 8 + tq * 2;
            *(unsigned*)&g_Wh16[(size_t)row * NB + col] =
                h22u(__floats2half2_rn(c[mt][nb][0], c[mt][nb][1]));
            *(unsigned*)&g_Wh16[(size_t)(row + 8) * NB + col] =
                h22u(__floats2half2_rn(c[mt][nb][2], c[mt][nb][3]));
        }
}

// ---------------------------------------------------------------------------
// K3: fused edge-gen + masked softmax + P@Wh + elu
// grid 128 x 256 thr; BM=64 rows/CTA; 64 col tiles of 128 (double-buffered)
// ---------------------------------------------------------------------------
#define MB0 0
#define MB1 8
#define L4O 16
#define PSO 1056
#define PS_B 17408           // 64 * 136 halves * 2B
#define BS0O 35968
#define BS_B 67584           // 128 * 264 halves * 2B
#define K3_SMEM (BS0O + 2 * BS_B)
#define BTILE 67584u
#define NT (NN / 128)        // 64 tiles

__global__ __launch_bounds__(256, 1) void attn_kernel(const int* __restrict__ adj,
                                                      float* __restrict__ out) {
    extern __shared__ __align__(128) char sm[];
    const uint32_t base = smem_u32(sm);
    float* l4 = (float*)(sm + L4O);

    const int tid = threadIdx.x;
    const int warp = tid >> 5, lane = tid & 31;
    const int wm = warp >> 2, wn = warp & 3;
    const int r = tid >> 2, q = tid & 3;
    const int row0 = blockIdx.x * 64;

    if (tid == 0) { MBAR_INIT(base + MB0, 1); MBAR_INIT(base + MB1, 1); }
    __syncthreads();

    const __half2 R2h = u2h2(g_R2[row0 + r]);
    const int4* arow = (const int4*)(adj + (size_t)(row0 + r) * NN);
    int4 av[8];
#pragma unroll
    for (int u = 0; u < 8; u++) av[u] = __ldcs(&arow[q * 8 + u]);   // tile 0

    if (tid == 0) {
        EXPECT_TX(base + MB0, BTILE);
        TMA_BULK(base + BS0O, (const void*)&g_Wh16[0], BTILE, base + MB0);
    }

    float lacc = 0.f;
    int ph0 = 0, ph1 = 0;
    float c[2][8][4];
#pragma unroll
    for (int a = 0; a < 2; a++)
#pragma unroll
        for (int b = 0; b < 8; b++)
#pragma unroll
            for (int d = 0; d < 4; d++) c[a][b][d] = 0.f;

    for (int t = 0; t < NT; t++) {
        const int b = t & 1;
        __half* Ps = (__half*)(sm + PSO + b * PS_B);

        // ---- kick TMA for t+1 into the other buffer ----
        if (t + 1 < NT && tid == 0) {
            uint32_t mb = base + ((1 - b) ? MB1 : MB0);
            uint32_t bs = base + BS0O + (1 - b) * BS_B;
            EXPECT_TX(mb, BTILE);
            TMA_BULK(bs, (const void*)&g_Wh16[(size_t)(t + 1) * 128 * NB], BTILE, mb);
        }

        // ---- edge-gen: p = mask * max(B, R*D), fp16; lacc in fp32 ----
        {
            const int hb = t * 64 + q * 16;   // half2 base index
            uint4 bu[4], du[4];
#pragma unroll
            for (int i = 0; i < 4; i++) {
                bu[i] = *(const uint4*)&g_B2[hb + i * 4];
                du[i] = *(const uint4*)&g_D2[hb + i * 4];
            }
            const unsigned* bb = (const unsigned*)bu;
            const unsigned* dd = (const unsigned*)du;
#pragma unroll
            for (int u = 0; u < 8; u++) {
                int4 a4 = av[u];
                unsigned mka = (a4.x > 0 ? 0x3C00u : 0u) | (a4.y > 0 ? 0x3C000000u : 0u);
                unsigned mkb = (a4.z > 0 ? 0x3C00u : 0u) | (a4.w > 0 ? 0x3C000000u : 0u);
                __half2 pa = __hmul2(__hmax2(u2h2(bb[u * 2]), __hmul2(R2h, u2h2(dd[u * 2]))),
                                     u2h2(mka));
                __half2 pb = __hmul2(__hmax2(u2h2(bb[u * 2 + 1]),
                                             __hmul2(R2h, u2h2(dd[u * 2 + 1]))),
                                     u2h2(mkb));
                *(uint2*)&Ps[r * 136 + q * 32 + u * 4] = make_uint2(h22u(pa), h22u(pb));
                float2 fa = __half22float2(pa), fb = __half22float2(pb);
                lacc += fa.x + fa.y + fb.x + fb.y;
            }
        }

        // ---- prefetch adjacency for t+1 ----
        if (t + 1 < NT) {
#pragma unroll
            for (int u = 0; u < 8; u++)
                av[u] = __ldcs(&arow[(t + 1) * 32 + q * 8 + u]);
        }

        // ---- wait B tile t, then sync so Ps is visible ----
        if (b == 0) { mbar_wait(base + MB0, ph0); ph0 ^= 1; }
        else        { mbar_wait(base + MB1, ph1); ph1 ^= 1; }
        __syncthreads();

        // ---- MMA: c += P[64 x 128] @ B[128k x 256n] ----
        const __half* Bs = (const __half*)(sm + BS0O + b * BS_B);
#pragma unroll
        for (int ks = 0; ks < 8; ks++) {
            unsigned a[2][4];
#pragma unroll
            for (int mt = 0; mt < 2; mt++)
                ldsm4(a[mt][0], a[mt][1], a[mt][2], a[mt][3],
                      smem_u32(&Ps[(wm * 32 + mt * 16 + (lane & 15)) * 136 +
                                   ks * 16 + ((lane >> 4) << 3)]));
#pragma unroll
            for (int np = 0; np < 4; np++) {
                unsigned b0, b1, b2, b3;
                ldsm4t(b0, b1, b2, b3,
                       smem_u32(&Bs[(ks * 16 + (lane & 15)) * 264 +
                                    wn * 64 + np * 16 + ((lane >> 4) << 3)]));
#pragma unroll
                for (int mt = 0; mt < 2; mt++) {
                    mma16816(c[mt][np * 2], a[mt][0], a[mt][1], a[mt][2], a[mt][3], b0, b1);
                    mma16816(c[mt][np * 2 + 1], a[mt][0], a[mt][1], a[mt][2], a[mt][3], b2, b3);
                }
            }
        }
        __syncthreads();   // Ps + Bs consumed before next iter overwrites
    }

    // ---- row-sum reduction ----
    l4[r * 4 + q] = lacc;
    __syncthreads();

    // ---- epilogue: normalize + elu + store ----
#pragma unroll
    for (int mt = 0; mt < 2; mt++) {
        int rl = wm * 32 + mt * 16 + (lane >> 2);
        float4 lv1 = *(float4*)&l4[rl * 4];
        float4 lv2 = *(float4*)&l4[(rl + 8) * 4];
        float inv1 = 1.f / (lv1.x + lv1.y + lv1.z + lv1.w);
        float inv2 = 1.f / (lv2.x + lv2.y + lv2.z + lv2.w);
#pragma unroll
        for (int nb = 0; nb < 8; nb++) {
            int col = wn * 64 + nb * 8 + (lane & 3) * 2;
            float x0 = c[mt][nb][0] * inv1, x1 = c[mt][nb][1] * inv1;
            float y0 = c[mt][nb][2] * inv2, y1 = c[mt][nb][3] * inv2;
            float2 v1 = make_float2(x0 > 0.f ? x0 : expm1f(x0),
                                    x1 > 0.f ? x1 : expm1f(x1));
            float2 v2 = make_float2(y0 > 0.f ? y0 : expm1f(y0),
                                    y1 > 0.f ? y1 : expm1f(y1));
            *(float2*)&out[(size_t)(row0 + rl) * DD + col] = v1;
            *(float2*)&out[(size_t)(row0 + rl + 8) * DD + col] = v2;
        }
    }
}

// ---------------------------------------------------------------------------
extern "C" void kernel_launch(void* const* d_in, const int* in_sizes, int n_in,
                              void* d_out, int out_size) {
    const float* X     = (const float*)d_in[0];
    const int*   adj   = (const int*)d_in[1];
    const float* W     = (const float*)d_in[2];
    const float* a_src = (const float*)d_in[3];
    const float* a_dst = (const float*)d_in[4];
    float* out = (float*)d_out;
    (void)in_sizes; (void)n_in; (void)out_size;

    cudaFuncSetAttribute(attn_kernel,
                         cudaFuncAttributeMaxDynamicSharedMemorySize, K3_SMEM);

    conv_x_kernel<<<(NN * DD) / 2048, 256>>>(X);
    conv_w_kernel<<<(DD * DD) / 2048, 256>>>(W);
    wvec_kernel<<<1, 256>>>(W, a_src, a_dst);
    fsfd_kernel<<<NN / 8, 256>>>(X);
    consts_kernel<<<NN / 256, 256>>>();
    wh_gemm_kernel<<<NN / 64, 256>>>();
    attn_kernel<<<NN / 64, 256, K3_SMEM>>>(adj, out);
}

// round 6
// speedup vs baseline: 36.0064x; 1.0954x over previous
#include <cuda_runtime.h>
#include <cuda_fp16.h>
#include <cstdint>
#include <cstddef>

#define NN 8192
#define DD 256
#define NB 264            // 256 dims + 8 halves pad -> 528B row

// ---------------- device scratch (no runtime alloc allowed) ----------------
__device__ __align__(128) __half g_Wh16[(size_t)NN * NB];
__device__ __align__(128) __half g_X16[(size_t)NN * DD];
__device__ __align__(128) __half g_W16[DD * DD];
__device__ float g_fs[NN], g_fd[NN];
__device__ float g_ws[DD], g_wd[DD];
__device__ unsigned g_R2[NN];        // half2(R_i, R_i),  R = exp(-0.8 fs)
__device__ unsigned g_B2[NN / 2];    // half2(B_2j, B_2j+1), B = exp(fd)
__device__ unsigned g_D2[NN / 2];    // half2(D_2j, D_2j+1), D = exp(0.2 fd)

// ---------------- helpers ----------------
__device__ __forceinline__ uint32_t smem_u32(const void* p) {
    uint32_t a;
    asm("{ .reg .u64 t; cvta.to.shared.u64 t, %1; cvt.u32.u64 %0, t; }" : "=r"(a) : "l"(p));
    return a;
}
__device__ __forceinline__ __half2 u2h2(unsigned u) { return *reinterpret_cast<__half2*>(&u); }
__device__ __forceinline__ unsigned h22u(__half2 h) { return *reinterpret_cast<unsigned*>(&h); }

#define CP16(dst, src)   asm volatile("cp.async.cg.shared.global [%0], [%1], 16;" :: "r"(dst), "l"(src))
#define CPCOMMIT()       asm volatile("cp.async.commit_group;" ::: "memory")
#define CPWAIT0()        asm volatile("cp.async.wait_group 0;" ::: "memory")
#define MBAR_INIT(mb, c) asm volatile("mbarrier.init.shared.b64 [%0], %1;" :: "r"(mb), "r"(c) : "memory")
#define MBAR_ARRIVE(mb)  asm volatile("mbarrier.arrive.shared.b64 _, [%0];" :: "r"(mb) : "memory")
#define EXPECT_TX(mb, n) asm volatile("mbarrier.arrive.expect_tx.shared.b64 _, [%0], %1;" :: "r"(mb), "r"(n) : "memory")
#define TMA_BULK(dst, src, bytes, mb) \
    asm volatile("cp.async.bulk.shared::cluster.global.mbarrier::complete_tx::bytes [%0], [%1], %2, [%3];" \
                 :: "r"(dst), "l"(src), "r"(bytes), "r"(mb) : "memory")

__device__ __forceinline__ void mbar_wait(uint32_t mb, uint32_t parity) {
    uint32_t done;
    asm volatile(
        "{\n\t.reg .pred p;\n\t"
        "mbarrier.try_wait.parity.shared.b64 p, [%1], %2;\n\t"
        "selp.b32 %0, 1, 0, p;\n\t}"
        : "=r"(done) : "r"(mb), "r"(parity) : "memory");
    if (!done) {
        asm volatile(
            "{\n\t.reg .pred P1;\n\t"
            "WL_%=:\n\t"
            "mbarrier.try_wait.parity.shared.b64 P1, [%0], %1;\n\t"
            "@P1 bra.uni WD_%=;\n\t"
            "bra.uni WL_%=;\n\t"
            "WD_%=:\n\t}"
            :: "r"(mb), "r"(parity) : "memory");
    }
}

__device__ __forceinline__ void ldsm4(unsigned &r0, unsigned &r1, unsigned &r2, unsigned &r3,
                                      uint32_t addr) {
    asm volatile("ldmatrix.sync.aligned.m8n8.x4.shared.b16 {%0,%1,%2,%3}, [%4];"
                 : "=r"(r0), "=r"(r1), "=r"(r2), "=r"(r3) : "r"(addr));
}
__device__ __forceinline__ void ldsm4t(unsigned &r0, unsigned &r1, unsigned &r2, unsigned &r3,
                                       uint32_t addr) {
    asm volatile("ldmatrix.sync.aligned.m8n8.x4.trans.shared.b16 {%0,%1,%2,%3}, [%4];"
                 : "=r"(r0), "=r"(r1), "=r"(r2), "=r"(r3) : "r"(addr));
}
__device__ __forceinline__ void mma16816(float* c, unsigned a0, unsigned a1, unsigned a2,
                                         unsigned a3, unsigned b0, unsigned b1) {
    asm volatile(
        "mma.sync.aligned.m16n8k16.row.col.f32.f16.f16.f32 "
        "{%0,%1,%2,%3}, {%4,%5,%6,%7}, {%8,%9}, {%0,%1,%2,%3};"
        : "+f"(c[0]), "+f"(c[1]), "+f"(c[2]), "+f"(c[3])
        : "r"(a0), "r"(a1), "r"(a2), "r"(a3), "r"(b0), "r"(b1));
}

// ---------------------------------------------------------------------------
// converts: fp32 -> fp16 (vectorized)
// ---------------------------------------------------------------------------
__global__ void conv_x_kernel(const float* __restrict__ X) {
    size_t i = ((size_t)blockIdx.x * 256 + threadIdx.x) * 8;
    float4 v0 = *(const float4*)&X[i];
    float4 v1 = *(const float4*)&X[i + 4];
    uint4 o;
    o.x = h22u(__floats2half2_rn(v0.x, v0.y));
    o.y = h22u(__floats2half2_rn(v0.z, v0.w));
    o.z = h22u(__floats2half2_rn(v1.x, v1.y));
    o.w = h22u(__floats2half2_rn(v1.z, v1.w));
    *(uint4*)&g_X16[i] = o;
}
__global__ void conv_w_kernel(const float* __restrict__ W) {
    size_t i = ((size_t)blockIdx.x * 256 + threadIdx.x) * 8;
    float4 v0 = *(const float4*)&W[i];
    float4 v1 = *(const float4*)&W[i + 4];
    uint4 o;
    o.x = h22u(__floats2half2_rn(v0.x, v0.y));
    o.y = h22u(__floats2half2_rn(v0.z, v0.w));
    o.z = h22u(__floats2half2_rn(v1.x, v1.y));
    o.w = h22u(__floats2half2_rn(v1.z, v1.w));
    *(uint4*)&g_W16[i] = o;
}

// ---------------------------------------------------------------------------
// wvec: w_src = W @ a_src ; w_dst = W @ a_dst   (1 CTA, 256 thr)
// ---------------------------------------------------------------------------
__global__ void wvec_kernel(const float* __restrict__ W, const float* __restrict__ a_src,
                            const float* __restrict__ a_dst) {
    int i = threadIdx.x;
    float s = 0.f, t = 0.f;
    const float4* wr = (const float4*)&W[(size_t)i * DD];
#pragma unroll 8
    for (int o = 0; o < DD / 4; o++) {
        float4 w = wr[o];
        float4 as = *(const float4*)&a_src[o * 4];
        float4 ad = *(const float4*)&a_dst[o * 4];
        s += w.x * as.x + w.y * as.y + w.z * as.z + w.w * as.w;
        t += w.x * ad.x + w.y * ad.y + w.z * ad.z + w.w * ad.w;
    }
    g_ws[i] = s;
    g_wd[i] = t;
}

// ---------------------------------------------------------------------------
// fsfd: fs = X @ w_src ; fd = X @ w_dst   (one warp per row, fp32)
// ---------------------------------------------------------------------------
__global__ __launch_bounds__(256) void fsfd_kernel(const float* __restrict__ X) {
    const int warp = threadIdx.x >> 5, lane = threadIdx.x & 31;
    const int row = blockIdx.x * 8 + warp;
    const float* xr = &X[(size_t)row * DD];
    float s = 0.f, t = 0.f;
#pragma unroll
    for (int k = lane; k < DD; k += 32) {
        float x = xr[k];
        s += x * g_ws[k];
        t += x * g_wd[k];
    }
#pragma unroll
    for (int o = 16; o > 0; o >>= 1) {
        s += __shfl_xor_sync(0xffffffffu, s, o);
        t += __shfl_xor_sync(0xffffffffu, t, o);
    }
    if (lane == 0) { g_fs[row] = s; g_fd[row] = t; }
}

// ---------------------------------------------------------------------------
// consts: R2[i] = half2(exp(-0.8 fs_i)); B2/D2 packed per col pair
// ---------------------------------------------------------------------------
__global__ void consts_kernel() {
    int i = blockIdx.x * 256 + threadIdx.x;
    float fs = g_fs[i];
    __half r = __float2half_rn(__expf(-0.8f * fs));
    g_R2[i] = h22u(__halves2half2(r, r));
    if (i < NN / 2) {
        float f0 = g_fd[2 * i], f1 = g_fd[2 * i + 1];
        g_B2[i] = h22u(__floats2half2_rn(__expf(f0), __expf(f1)));
        g_D2[i] = h22u(__floats2half2_rn(__expf(0.2f * f0), __expf(0.2f * f1)));
    }
}

// ---------------------------------------------------------------------------
// K1: Wh16 = X16 @ W16  via mma.sync + cp.async tiles
// ---------------------------------------------------------------------------
__global__ __launch_bounds__(256) void wh_gemm_kernel() {
    __shared__ __align__(16) __half Xs[64 * 72];
    __shared__ __align__(16) __half Wsm[64 * 264];
    const int tid = threadIdx.x;
    const int warp = tid >> 5, lane = tid & 31;
    const int wm = warp >> 2, wn = warp & 3;
    const int row0 = blockIdx.x * 64;

    float c[2][8][4];
#pragma unroll
    for (int a = 0; a < 2; a++)
#pragma unroll
        for (int b = 0; b < 8; b++)
#pragma unroll
            for (int d = 0; d < 4; d++) c[a][b][d] = 0.f;

    for (int kt = 0; kt < 4; kt++) {
#pragma unroll
        for (int i = 0; i < 2; i++) {
            int ci = i * 256 + tid;
            int r = ci >> 3, o = ci & 7;
            CP16(smem_u32(&Xs[r * 72 + o * 8]),
                 &g_X16[(size_t)(row0 + r) * DD + kt * 64 + o * 8]);
        }
#pragma unroll
        for (int i = 0; i < 8; i++) {
            int ci = i * 256 + tid;
            int r = ci >> 5, o = ci & 31;
            CP16(smem_u32(&Wsm[r * 264 + o * 8]),
                 &g_W16[(size_t)(kt * 64 + r) * DD + o * 8]);
        }
        CPCOMMIT();
        CPWAIT0();
        __syncthreads();

#pragma unroll
        for (int ks = 0; ks < 4; ks++) {
            unsigned a[2][4];
#pragma unroll
            for (int mt = 0; mt < 2; mt++)
                ldsm4(a[mt][0], a[mt][1], a[mt][2], a[mt][3],
                      smem_u32(&Xs[(wm * 32 + mt * 16 + (lane & 15)) * 72 +
                                   ks * 16 + ((lane >> 4) << 3)]));
#pragma unroll
            for (int np = 0; np < 4; np++) {
                unsigned b0, b1, b2, b3;
                ldsm4t(b0, b1, b2, b3,
                       smem_u32(&Wsm[(ks * 16 + (lane & 15)) * 264 +
                                     wn * 64 + np * 16 + ((lane >> 4) << 3)]));
#pragma unroll
                for (int mt = 0; mt < 2; mt++) {
                    mma16816(c[mt][np * 2], a[mt][0], a[mt][1], a[mt][2], a[mt][3], b0, b1);
                    mma16816(c[mt][np * 2 + 1], a[mt][0], a[mt][1], a[mt][2], a[mt][3], b2, b3);
                }
            }
        }
        __syncthreads();
    }

    const int g = lane >> 2, tq = lane & 3;
#pragma unroll
    for (int mt = 0; mt < 2; mt++)
#pragma unroll
        for (int nb = 0; nb < 8; nb++) {
            int row = row0 + wm * 32 + mt * 16 + g;
            int col = wn * 64 + nb * 8 + tq * 2;
            *(unsigned*)&g_Wh16[(size_t)row * NB + col] =
                h22u(__floats2half2_rn(c[mt][nb][0], c[mt][nb][1]));
            *(unsigned*)&g_Wh16[(size_t)(row + 8) * NB + col] =
                h22u(__floats2half2_rn(c[mt][nb][2], c[mt][nb][3]));
        }
}

// ---------------------------------------------------------------------------
// K3: warp-specialized fused attn.
// 384 threads: warps 0-7 = MMA consumers (256 thr), warps 8-11 = producers.
// 64 col-tiles of 128; P and B both double-buffered; mbarrier ring depth 2.
// smem barriers: PF[2]@0, PE[2]@16, BF[2]@32, BE[2]@48
// ---------------------------------------------------------------------------
#define PFB(s) (0 + 8 * (s))
#define PEB(s) (16 + 8 * (s))
#define BFB(s) (32 + 8 * (s))
#define BEB(s) (48 + 8 * (s))
#define L4O 64
#define PSO 1024
#define PS_B 17408           // 64 * 136 halves * 2B
#define BS0O (PSO + 2 * PS_B)          // 35840
#define BS_B 67584                     // 128 * 264 halves * 2B
#define K3_SMEM (BS0O + 2 * BS_B)      // 171008
#define BTILE 67584u
#define NT (NN / 128)        // 64 tiles

__global__ __launch_bounds__(384, 1) void attn_kernel(const int* __restrict__ adj,
                                                      float* __restrict__ out) {
    extern __shared__ __align__(128) char sm[];
    const uint32_t base = smem_u32(sm);
    float* l4 = (float*)(sm + L4O);

    const int tid = threadIdx.x;
    const int warp = tid >> 5, lane = tid & 31;
    const int row0 = blockIdx.x * 64;

    if (tid == 0) {
#pragma unroll
        for (int s = 0; s < 2; s++) {
            MBAR_INIT(base + PFB(s), 128);
            MBAR_INIT(base + PEB(s), 256);
            MBAR_INIT(base + BFB(s), 1);
            MBAR_INIT(base + BEB(s), 256);
        }
    }
    __syncthreads();

    if (warp >= 8) {
        // ================= PRODUCER warps (128 threads) =================
        const int ptid = tid - 256;
        const int r = ptid >> 1, h = ptid & 1;       // row, 64-col half
        const __half2 R2h = u2h2(g_R2[row0 + r]);
        const int4* arow = (const int4*)(adj + (size_t)(row0 + r) * NN);
        float lacc = 0.f;
        int pe_ph0 = 0, pe_ph1 = 0, be_ph0 = 0, be_ph1 = 0;

        if (ptid == 0) {
            EXPECT_TX(base + BFB(0), BTILE);
            TMA_BULK(base + BS0O, (const void*)&g_Wh16[0], BTILE, base + BFB(0));
        }

        for (int t = 0; t < NT; t++) {
            const int b = t & 1;
            __half* Ps = (__half*)(sm + PSO + b * PS_B);

            // TMA for tile t+1 into stage (t+1)&1
            if (ptid == 0 && t + 1 < NT) {
                const int b2 = (t + 1) & 1;
                if (t + 1 >= 2) {
                    if (b2 == 0) { mbar_wait(base + BEB(0), be_ph0); be_ph0 ^= 1; }
                    else         { mbar_wait(base + BEB(1), be_ph1); be_ph1 ^= 1; }
                }
                EXPECT_TX(base + BFB(b2), BTILE);
                TMA_BULK(base + BS0O + b2 * BS_B,
                         (const void*)&g_Wh16[(size_t)(t + 1) * 128 * NB], BTILE,
                         base + BFB(b2));
            }

            // wait until MMA released this P stage (t-2 consumed)
            if (t >= 2) {
                if (b == 0) { mbar_wait(base + PEB(0), pe_ph0); pe_ph0 ^= 1; }
                else        { mbar_wait(base + PEB(1), pe_ph1); pe_ph1 ^= 1; }
            }

            // edge-gen: 64 cols for (r, h)
            const int cb = t * 128 + h * 64;
            const int hb = cb >> 1;
            uint4 bu[8], du[8];
#pragma unroll
            for (int i = 0; i < 8; i++) {
                bu[i] = *(const uint4*)&g_B2[hb + i * 4];
                du[i] = *(const uint4*)&g_D2[hb + i * 4];
            }
            const unsigned* bb = (const unsigned*)bu;
            const unsigned* dd = (const unsigned*)du;
            int4 a4[16];
#pragma unroll
            for (int u = 0; u < 16; u++) a4[u] = __ldcs(&arow[cb / 4 + u]);
#pragma unroll
            for (int u = 0; u < 16; u++) {
                unsigned mka = (a4[u].x > 0 ? 0x3C00u : 0u) | (a4[u].y > 0 ? 0x3C000000u : 0u);
                unsigned mkb = (a4[u].z > 0 ? 0x3C00u : 0u) | (a4[u].w > 0 ? 0x3C000000u : 0u);
                __half2 pa = __hmul2(__hmax2(u2h2(bb[u * 2]), __hmul2(R2h, u2h2(dd[u * 2]))),
                                     u2h2(mka));
                __half2 pb = __hmul2(__hmax2(u2h2(bb[u * 2 + 1]),
                                             __hmul2(R2h, u2h2(dd[u * 2 + 1]))),
                                     u2h2(mkb));
                *(uint2*)&Ps[r * 136 + h * 64 + u * 4] = make_uint2(h22u(pa), h22u(pb));
                float2 fa = __half22float2(pa), fb = __half22float2(pb);
                lacc += fa.x + fa.y + fb.x + fb.y;
            }
            MBAR_ARRIVE(base + PFB(b));
        }
        l4[r * 2 + h] = lacc;
        __syncthreads();   // join with consumers
    } else {
        // ================= MMA warps (256 threads) =================
        const int wm = warp >> 2, wn = warp & 3;
        int pf_ph0 = 0, pf_ph1 = 0, bf_ph0 = 0, bf_ph1 = 0;

        float c[2][8][4];
#pragma unroll
        for (int a = 0; a < 2; a++)
#pragma unroll
            for (int b = 0; b < 8; b++)
#pragma unroll
                for (int d = 0; d < 4; d++) c[a][b][d] = 0.f;

        for (int t = 0; t < NT; t++) {
            const int b = t & 1;
            const __half* Ps = (const __half*)(sm + PSO + b * PS_B);
            const __half* Bs = (const __half*)(sm + BS0O + b * BS_B);

            if (b == 0) {
                mbar_wait(base + PFB(0), pf_ph0); pf_ph0 ^= 1;
                mbar_wait(base + BFB(0), bf_ph0); bf_ph0 ^= 1;
            } else {
                mbar_wait(base + PFB(1), pf_ph1); pf_ph1 ^= 1;
                mbar_wait(base + BFB(1), bf_ph1); bf_ph1 ^= 1;
            }

#pragma unroll
            for (int ks = 0; ks < 8; ks++) {
                unsigned a[2][4];
#pragma unroll
                for (int mt = 0; mt < 2; mt++)
                    ldsm4(a[mt][0], a[mt][1], a[mt][2], a[mt][3],
                          smem_u32(&Ps[(wm * 32 + mt * 16 + (lane & 15)) * 136 +
                                       ks * 16 + ((lane >> 4) << 3)]));
#pragma unroll
                for (int np = 0; np < 4; np++) {
                    unsigned b0, b1, b2, b3;
                    ldsm4t(b0, b1, b2, b3,
                           smem_u32(&Bs[(ks * 16 + (lane & 15)) * 264 +
                                        wn * 64 + np * 16 + ((lane >> 4) << 3)]));
#pragma unroll
                    for (int mt = 0; mt < 2; mt++) {
                        mma16816(c[mt][np * 2], a[mt][0], a[mt][1], a[mt][2], a[mt][3], b0, b1);
                        mma16816(c[mt][np * 2 + 1], a[mt][0], a[mt][1], a[mt][2], a[mt][3], b2, b3);
                    }
                }
            }
            MBAR_ARRIVE(base + PEB(b));
            MBAR_ARRIVE(base + BEB(b));
        }

        __syncthreads();   // l4 ready

        // ---- epilogue: normalize + elu + store ----
#pragma unroll
        for (int mt = 0; mt < 2; mt++) {
            int rl = wm * 32 + mt * 16 + (lane >> 2);
            float inv1 = 1.f / (l4[rl * 2] + l4[rl * 2 + 1]);
            float inv2 = 1.f / (l4[(rl + 8) * 2] + l4[(rl + 8) * 2 + 1]);
#pragma unroll
            for (int nb = 0; nb < 8; nb++) {
                int col = wn * 64 + nb * 8 + (lane & 3) * 2;
                float x0 = c[mt][nb][0] * inv1, x1 = c[mt][nb][1] * inv1;
                float y0 = c[mt][nb][2] * inv2, y1 = c[mt][nb][3] * inv2;
                float2 v1 = make_float2(x0 > 0.f ? x0 : expm1f(x0),
                                        x1 > 0.f ? x1 : expm1f(x1));
                float2 v2 = make_float2(y0 > 0.f ? y0 : expm1f(y0),
                                        y1 > 0.f ? y1 : expm1f(y1));
                *(float2*)&out[(size_t)(row0 + rl) * DD + col] = v1;
                *(float2*)&out[(size_t)(row0 + rl + 8) * DD + col] = v2;
            }
        }
    }
}

// ---------------------------------------------------------------------------
extern "C" void kernel_launch(void* const* d_in, const int* in_sizes, int n_in,
                              void* d_out, int out_size) {
    const float* X     = (const float*)d_in[0];
    const int*   adj   = (const int*)d_in[1];
    const float* W     = (const float*)d_in[2];
    const float* a_src = (const float*)d_in[3];
    const float* a_dst = (const float*)d_in[4];
    float* out = (float*)d_out;
    (void)in_sizes; (void)n_in; (void)out_size;

    cudaFuncSetAttribute(attn_kernel,
                         cudaFuncAttributeMaxDynamicSharedMemorySize, K3_SMEM);

    conv_x_kernel<<<(NN * DD) / 2048, 256>>>(X);
    conv_w_kernel<<<(DD * DD) / 2048, 256>>>(W);
    wvec_kernel<<<1, 256>>>(W, a_src, a_dst);
    fsfd_kernel<<<NN / 8, 256>>>(X);
    consts_kernel<<<NN / 256, 256>>>();
    wh_gemm_kernel<<<NN / 64, 256>>>();
    attn_kernel<<<NN / 64, 384, K3_SMEM>>>(adj, out);
}